// round 11
// baseline (speedup 1.0000x reference)
#include <cuda_runtime.h>
#include <cstdint>

#define N_PTS   4096
#define DIM     128
#define TOPK    4
#define NCELL   4096            // 16^3 Morton cells
#define NBLK    64              // 4096 / 64 points per bounding block

// ---------------- global scratch ----------------
__device__ float4 SortedPos[2 * N_PTS];          // sorted positions, w = -0.5*|p|^2
__device__ int    PermBuf[2 * N_PTS];            // sorted -> original index (batch-local)
__device__ float4 BlkBnd[2 * NBLK];              // bounding spheres {cx,cy,cz,rad}
__device__ float  Z_buf[2 * N_PTS * DIM];        // x @ W
__device__ float4 WgtBuf[2 * N_PTS];             // normalized weights (by ORIGINAL row)
__device__ int4   IdxBuf[2 * N_PTS];             // original neighbor indices (by ORIGINAL row)

#define BUBBLE5(k)                                            \
    { float _t, _k = (k);                                     \
      _t = fminf(s0, _k); _k = fmaxf(s0, _k); s0 = _t;        \
      _t = fminf(s1, _k); _k = fmaxf(s1, _k); s1 = _t;        \
      _t = fminf(s2, _k); _k = fmaxf(s2, _k); s2 = _t;        \
      _t = fminf(s3, _k); _k = fmaxf(s3, _k); s3 = _t;        \
      s4 = fminf(s4, _k); }

#define SWP(a,b) { unsigned long long _t; if (a > b) { _t = a; a = b; b = _t; } }

#define TREEMERGE()                                                        \
    _Pragma("unroll")                                                      \
    for (int step = 8; step >= 1; step >>= 1) {                            \
        if (warp >= step && warp < 2 * step) {                             \
            float* m = m_s + ((warp - step) * 32 + lane) * 5;              \
            m[0] = s0; m[1] = s1; m[2] = s2; m[3] = s3; m[4] = s4;         \
        }                                                                  \
        __syncthreads();                                                   \
        if (warp < step) {                                                 \
            const float* m = m_s + (warp * 32 + lane) * 5;                 \
            BUBBLE5(m[0]); BUBBLE5(m[1]); BUBBLE5(m[2]);                   \
            BUBBLE5(m[3]); BUBBLE5(m[4]);                                  \
        }                                                                  \
        __syncthreads();                                                   \
    }

__device__ __forceinline__ unsigned spread4(unsigned v)
{   // 4 bits -> every 3rd bit
    return (v & 1u) | ((v & 2u) << 2) | ((v & 4u) << 4) | ((v & 8u) << 6);
}

// ---------------- kernel 1: per-batch Morton counting sort + block bounds ----------------
__global__ void __launch_bounds__(1024, 1)
sort_cells(const float* __restrict__ pos)
{
    __shared__ int cnt[NCELL];
    __shared__ int off[NCELL];

    const int b    = blockIdx.x;
    const int tid  = threadIdx.x;
    const int gb   = b * N_PTS;
    const float* pb = pos + (size_t)gb * 3;

    for (int k = tid; k < NCELL; k += 1024) cnt[k] = 0;
    __syncthreads();

    int mycell[4];
    #pragma unroll
    for (int k = 0; k < 4; k++) {
        int i = tid + k * 1024;
        float x = pb[3*i], y = pb[3*i+1], z = pb[3*i+2];
        int cx = min(15, max(0, __float2int_rd((x + 6.0f) * (16.0f / 12.0f))));
        int cy = min(15, max(0, __float2int_rd((y + 6.0f) * (16.0f / 12.0f))));
        int cz = min(15, max(0, __float2int_rd((z + 6.0f) * (16.0f / 12.0f))));
        int cell = (int)(spread4((unsigned)cx) | (spread4((unsigned)cy) << 1)
                       | (spread4((unsigned)cz) << 2));
        mycell[k] = cell;
        atomicAdd(&cnt[cell], 1);
    }
    __syncthreads();

    // Hillis-Steele inclusive scan, ping-pong; 12 passes -> result back in cnt
    int* src = cnt; int* dst = off;
    for (int d = 1; d < NCELL; d <<= 1) {
        for (int k = tid; k < NCELL; k += 1024) {
            int v = src[k];
            if (k >= d) v += src[k - d];
            dst[k] = v;
        }
        __syncthreads();
        int* t = src; src = dst; dst = t;
    }
    // src == cnt (inclusive). exclusive into off.
    for (int k = tid; k < NCELL; k += 1024) off[k] = (k == 0) ? 0 : src[k - 1];
    __syncthreads();

    // scatter
    #pragma unroll
    for (int k = 0; k < 4; k++) {
        int i = tid + k * 1024;
        int dstp = atomicAdd(&off[mycell[k]], 1);
        float x = pb[3*i], y = pb[3*i+1], z = pb[3*i+2];
        SortedPos[gb + dstp] = make_float4(x, y, z,
            -0.5f * fmaf(z, z, fmaf(y, y, x * x)));
        PermBuf[gb + dstp] = i;
    }
    __syncthreads();

    // per-64-point bounding spheres (32 warps x 2 blocks)
    const int warp = tid >> 5;
    const int lane = tid & 31;
    for (int t = warp; t < NBLK; t += 32) {
        float4 p0 = SortedPos[gb + t * 64 + lane];
        float4 p1 = SortedPos[gb + t * 64 + 32 + lane];
        float mnx = fminf(p0.x, p1.x), mxx = fmaxf(p0.x, p1.x);
        float mny = fminf(p0.y, p1.y), mxy = fmaxf(p0.y, p1.y);
        float mnz = fminf(p0.z, p1.z), mxz = fmaxf(p0.z, p1.z);
        #pragma unroll
        for (int o = 16; o; o >>= 1) {
            mnx = fminf(mnx, __shfl_xor_sync(0xffffffffu, mnx, o));
            mxx = fmaxf(mxx, __shfl_xor_sync(0xffffffffu, mxx, o));
            mny = fminf(mny, __shfl_xor_sync(0xffffffffu, mny, o));
            mxy = fmaxf(mxy, __shfl_xor_sync(0xffffffffu, mxy, o));
            mnz = fminf(mnz, __shfl_xor_sync(0xffffffffu, mnz, o));
            mxz = fmaxf(mxz, __shfl_xor_sync(0xffffffffu, mxz, o));
        }
        if (lane == 0) {
            float dx = 0.5f * (mxx - mnx);
            float dy = 0.5f * (mxy - mny);
            float dz = 0.5f * (mxz - mnz);
            float rad = sqrtf(fmaf(dz, dz, fmaf(dy, dy, dx * dx))) + 1e-5f;
            BlkBnd[b * NBLK + t] = make_float4(0.5f * (mnx + mxx),
                                               0.5f * (mny + mxy),
                                               0.5f * (mnz + mxz), rad);
        }
    }
}

// ---------------- kernel 2: Z = x @ W (proven R2 inner, 64 rows/block) ----------------
#define GA_THREADS 512
#define GA_ROWS    64

__global__ void __launch_bounds__(GA_THREADS, 2)
gemm_xw(const float* __restrict__ x, const float* __restrict__ W)
{
    extern __shared__ float smemA[];
    float4* W_s = (float4*)smemA;             // 128*32 float4 = 64 KB
    float*  x_s = (float*)(W_s + DIM * 32);   // 64*128 floats = 32 KB

    const int tid = threadIdx.x;
    const int g0  = blockIdx.x * GA_ROWS;

    const float4* W4 = (const float4*)W;
    #pragma unroll
    for (int i = tid; i < DIM * 32; i += GA_THREADS) W_s[i] = W4[i];

    const float4* xg = (const float4*)x + (size_t)g0 * 32;
    float4* xs4 = (float4*)x_s;
    #pragma unroll
    for (int i = tid; i < GA_ROWS * 32; i += GA_THREADS) xs4[i] = xg[i];
    __syncthreads();

    const int warp = tid >> 5;
    const int lane = tid & 31;
    const float* xr = x_s + warp * 4 * DIM;

    float4 a0 = make_float4(0.f,0.f,0.f,0.f);
    float4 a1 = a0, a2 = a0, a3 = a0;

    #pragma unroll 4
    for (int d = 0; d < DIM; d++) {
        float4 wv = W_s[d * 32 + lane];
        float y0 = xr[d];
        float y1 = xr[d + DIM];
        float y2 = xr[d + 2*DIM];
        float y3 = xr[d + 3*DIM];
        a0.x = fmaf(y0, wv.x, a0.x); a0.y = fmaf(y0, wv.y, a0.y);
        a0.z = fmaf(y0, wv.z, a0.z); a0.w = fmaf(y0, wv.w, a0.w);
        a1.x = fmaf(y1, wv.x, a1.x); a1.y = fmaf(y1, wv.y, a1.y);
        a1.z = fmaf(y1, wv.z, a1.z); a1.w = fmaf(y1, wv.w, a1.w);
        a2.x = fmaf(y2, wv.x, a2.x); a2.y = fmaf(y2, wv.y, a2.y);
        a2.z = fmaf(y2, wv.z, a2.z); a2.w = fmaf(y2, wv.w, a2.w);
        a3.x = fmaf(y3, wv.x, a3.x); a3.y = fmaf(y3, wv.y, a3.y);
        a3.z = fmaf(y3, wv.z, a3.z); a3.w = fmaf(y3, wv.w, a3.w);
    }

    float4* Z4 = (float4*)Z_buf;
    const size_t r = (size_t)g0 + warp * 4;
    Z4[(r + 0) * 32 + lane] = a0;
    Z4[(r + 1) * 32 + lane] = a1;
    Z4[(r + 2) * 32 + lane] = a2;
    Z4[(r + 3) * 32 + lane] = a3;
}

// ---------------- kernel 3: pruned top-4 scan over sorted points ----------------
// 256 blocks; block = 32 sorted-consecutive rows (row-per-lane), 16 warps.
// tau from 128 sorted-adjacent samples; bound-check 64 blocks; scan passing only.

#define SC_THREADS 512

__global__ void __launch_bounds__(SC_THREADS, 3)
scan_topk()
{
    extern __shared__ float smemB[];
    float4* pos_s = (float4*)smemB;                    // [4096]
    float4* bnd_s = pos_s + N_PTS;                     // [64]
    float*  m_s   = (float*)(bnd_s + NBLK);            // [8*32*5]
    float*  tau_s = m_s + 8 * 32 * 5;                  // [32]
    int*    plist = (int*)(tau_s + 32);                // [64]
    int*    pcnt  = plist + NBLK;                      // [1]

    const int tid  = threadIdx.x;
    const int warp = tid >> 5;
    const int lane = tid & 31;
    const int rb   = blockIdx.x;                       // 0..255
    const int b    = rb >> 7;                          // 128 row-groups per batch
    const int n0   = (rb & 127) * 32;                  // sorted row base
    const int gb   = b * N_PTS;

    for (int i = tid; i < N_PTS; i += SC_THREADS) pos_s[i] = SortedPos[gb + i];
    for (int i = tid; i < NBLK; i += SC_THREADS)  bnd_s[i] = BlkBnd[b * NBLK + i];
    if (tid == 0) *pcnt = 0;
    __syncthreads();

    const float4 P   = pos_s[n0 + lane];
    const float  Pw2 = -2.0f * P.w;                    // |pi|^2

    const float INF = __int_as_float(0x7f800000);
    float s0 = INF, s1 = INF, s2 = INF, s3 = INF, s4 = INF;

    // ---- tau phase: 128 sorted-adjacent samples (8 per warp), full bubble ----
    int lo = n0 - 48;
    lo = lo < 0 ? 0 : (lo > N_PTS - 128 ? N_PTS - 128 : lo);
    const int tb = lo + warp * 8;
    #pragma unroll
    for (int jj = 0; jj < 8; jj++) {
        const int j = tb + jj;
        float4 q = pos_s[j];
        float t   = fmaf(P.x, q.x, fmaf(P.y, q.y, fmaf(P.z, q.z, q.w)));
        float d2c = fmaf(-2.0f, t, Pw2);
        float k   = __int_as_float((__float_as_int(d2c) & 0xFFFFF000) | j);
        BUBBLE5(k);
    }
    TREEMERGE();
    if (warp == 0)
        tau_s[lane] = __int_as_float((__float_as_int(s4) & 0xFFFFF000) + 0x1000);
    __syncthreads();

    const float tau = tau_s[lane];
    const float st  = sqrtf(fmaxf(tau, 0.0f)) * 1.002f + 2e-3f;

    // ---- bound check: warp w owns blocks [4w, 4w+4) ----
    #pragma unroll
    for (int t2 = warp * 4; t2 < warp * 4 + 4; t2++) {
        float4 bb = bnd_s[t2];
        float dx = P.x - bb.x, dy = P.y - bb.y, dz = P.z - bb.z;
        float d2b = fmaf(dz, dz, fmaf(dy, dy, dx * dx));
        float thr = bb.w + st;
        bool need = d2b < thr * thr;
        if (__any_sync(0xffffffffu, need)) {
            if (lane == 0) { int s = atomicAdd(pcnt, 1); plist[s] = t2; }
        }
    }
    __syncthreads();
    const int PN = *pcnt;

    // ---- filtered scan of passing blocks only (tau samples discarded: no dups) ----
    s0 = INF; s1 = INF; s2 = INF; s3 = INF; s4 = INF;
    for (int q2 = warp; q2 < PN; q2 += 16) {
        const int cb2 = plist[q2] * 64;
        #pragma unroll 8
        for (int jj = 0; jj < 64; jj++) {
            const int j = cb2 + jj;
            float4 q = pos_s[j];
            float t   = fmaf(P.x, q.x, fmaf(P.y, q.y, fmaf(P.z, q.z, q.w)));
            float d2c = fmaf(-2.0f, t, Pw2);
            if (d2c < tau) {
                float k = __int_as_float((__float_as_int(d2c) & 0xFFFFF000) | j);
                BUBBLE5(k);
            }
        }
    }
    TREEMERGE();

    // ---- warp 0: exact rerank, weights, write by ORIGINAL row ----
    if (warp == 0) {
        float cand[5] = { s0, s1, s2, s3, s4 };
        unsigned long long k[5];
        #pragma unroll
        for (int i = 0; i < 5; i++) {
            int js = __float_as_int(cand[i]) & 0xFFF;   // sorted index
            float4 q = pos_s[js];
            float dx = P.x - q.x, dy = P.y - q.y, dz = P.z - q.z;
            float d2 = fmaf(dz, dz, fmaf(dy, dy, dx * dx));
            unsigned oj = (unsigned)__ldg(&PermBuf[gb + js]);   // original index
            k[i] = ((unsigned long long)__float_as_uint(d2) << 32) | oj;
        }
        SWP(k[0],k[1]) SWP(k[3],k[4]) SWP(k[2],k[4]) SWP(k[2],k[3]) SWP(k[0],k[3])
        SWP(k[0],k[2]) SWP(k[1],k[4]) SWP(k[1],k[3]) SWP(k[1],k[2])

        float w0,w1,w2,w3; int i0,i1,i2,i3;
        float d2v;
        d2v = __uint_as_float((unsigned)(k[0] >> 32)); w0 = expf(-0.5f*(d2v+1e-8f)); i0 = (int)(k[0] & 0xFFFFFFFFull);
        d2v = __uint_as_float((unsigned)(k[1] >> 32)); w1 = expf(-0.5f*(d2v+1e-8f)); i1 = (int)(k[1] & 0xFFFFFFFFull);
        d2v = __uint_as_float((unsigned)(k[2] >> 32)); w2 = expf(-0.5f*(d2v+1e-8f)); i2 = (int)(k[2] & 0xFFFFFFFFull);
        d2v = __uint_as_float((unsigned)(k[3] >> 32)); w3 = expf(-0.5f*(d2v+1e-8f)); i3 = (int)(k[3] & 0xFFFFFFFFull);
        float inv = 1.0f / (((w0 + w1) + w2) + w3 + 1e-8f);

        const int orow = __ldg(&PermBuf[gb + n0 + lane]);       // original row
        WgtBuf[gb + orow] = make_float4(w0*inv, w1*inv, w2*inv, w3*inv);
        IdxBuf[gb + orow] = make_int4(i0, i1, i2, i3);
    }
}

// ---------------- kernel 4: gather Z + bias ----------------
#define GC_THREADS 256
#define GC_WARPS   8

__global__ void __launch_bounds__(GC_THREADS, 8)
finish_gather(const float* __restrict__ bias,
              float* __restrict__ out)
{
    const int tid  = threadIdx.x;
    const int warp = tid >> 5;
    const int lane = tid & 31;
    const int row  = blockIdx.x * GC_WARPS + warp;     // global original row
    const int b    = row >> 12;

    const float4 w4 = __ldg(&WgtBuf[row]);
    const int4   id = __ldg(&IdxBuf[row]);

    const float4* Z4 = (const float4*)Z_buf + (size_t)b * N_PTS * 32;
    float4 acc = __ldg(&((const float4*)bias)[lane]);
    float4 z0 = Z4[(size_t)id.x * 32 + lane];
    float4 z1 = Z4[(size_t)id.y * 32 + lane];
    float4 z2 = Z4[(size_t)id.z * 32 + lane];
    float4 z3 = Z4[(size_t)id.w * 32 + lane];
    acc.x = fmaf(w4.x,z0.x, fmaf(w4.y,z1.x, fmaf(w4.z,z2.x, fmaf(w4.w,z3.x, acc.x))));
    acc.y = fmaf(w4.x,z0.y, fmaf(w4.y,z1.y, fmaf(w4.z,z2.y, fmaf(w4.w,z3.y, acc.y))));
    acc.z = fmaf(w4.x,z0.z, fmaf(w4.y,z1.z, fmaf(w4.z,z2.z, fmaf(w4.w,z3.z, acc.z))));
    acc.w = fmaf(w4.x,z0.w, fmaf(w4.y,z1.w, fmaf(w4.z,z2.w, fmaf(w4.w,z3.w, acc.w))));
    ((float4*)out)[(size_t)row * 32 + lane] = acc;
}

extern "C" void kernel_launch(void* const* d_in, const int* in_sizes, int n_in,
                              void* d_out, int out_size)
{
    const float* x    = (const float*)d_in[0];
    const float* pos  = (const float*)d_in[1];
    const float* W    = (const float*)d_in[2];
    const float* bias = (const float*)d_in[3];
    float* out        = (float*)d_out;

    const int rows = in_sizes[1] / 3;                  // B * N = 8192

    // 1) Morton counting sort + bounds (one block per batch)
    sort_cells<<<rows / N_PTS, 1024>>>(pos);

    // 2) Z = x @ W (independent of sort)
    const size_t smemA = (size_t)DIM * 32 * 16 + (size_t)GA_ROWS * DIM * 4;   // 96 KB
    cudaFuncSetAttribute(gemm_xw, cudaFuncAttributeMaxDynamicSharedMemorySize, (int)smemA);
    gemm_xw<<<rows / GA_ROWS, GA_THREADS, smemA>>>(x, W);

    // 3) pruned scan
    const size_t smemB = (size_t)N_PTS * 16            // pos_s     65536
                       + (size_t)NBLK * 16             // bnd_s      1024
                       + 8 * 32 * 5 * 4                // m_s        5120
                       + 32 * 4                        // tau_s       128
                       + NBLK * 4 + 4;                 // plist+cnt   260
    cudaFuncSetAttribute(scan_topk, cudaFuncAttributeMaxDynamicSharedMemorySize, (int)smemB);
    scan_topk<<<(rows / 32), SC_THREADS, smemB>>>();

    // 4) gather + bias
    finish_gather<<<rows / GC_WARPS, GC_THREADS>>>(bias, out);
}

// round 12
// speedup vs baseline: 1.1552x; 1.1552x over previous
#include <cuda_runtime.h>
#include <cstdint>

#define N_PTS   4096
#define DIM     128
#define TOPK    4

// ---------------- global scratch ----------------
__device__ float Z_buf[2 * N_PTS * DIM];                 // x @ W  (4 MB)
__device__ unsigned long long Top5x[2 * N_PTS * 16];     // per row: [half][8] exact sorted u64 keys (5 used)

#define BUBBLE5(k)                                            \
    { float _t, _k = (k);                                     \
      _t = fminf(s0, _k); _k = fmaxf(s0, _k); s0 = _t;        \
      _t = fminf(s1, _k); _k = fmaxf(s1, _k); s1 = _t;        \
      _t = fminf(s2, _k); _k = fmaxf(s2, _k); s2 = _t;        \
      _t = fminf(s3, _k); _k = fmaxf(s3, _k); s3 = _t;        \
      s4 = fminf(s4, _k); }

#define SWP(a,b) { unsigned long long _t; if (a > b) { _t = a; a = b; b = _t; } }

// ---------------- kernel 1: interleaved scan / GEMM roles ----------------
// blockIdx % 3 in {0,1}: scan role (512 blocks) — R10 logic verbatim
// blockIdx % 3 == 2:      GEMM role (256 blocks) — 64 rows x 64 cols, 4 rows/warp

#define K1_THREADS 512
#define SB_WARPS   16
#define HALF_C     (N_PTS / 2)              // 2048
#define SB_SLICE   (HALF_C / SB_WARPS)      // 128
#define SB_L1      32

#define TREEMERGE()                                                        \
    _Pragma("unroll")                                                      \
    for (int step = 8; step >= 1; step >>= 1) {                            \
        if (warp >= step && warp < 2 * step) {                             \
            float* m = m_s + ((warp - step) * 32 + lane) * 5;              \
            m[0] = s0; m[1] = s1; m[2] = s2; m[3] = s3; m[4] = s4;         \
        }                                                                  \
        __syncthreads();                                                   \
        if (warp < step) {                                                 \
            const float* m = m_s + (warp * 32 + lane) * 5;                 \
            BUBBLE5(m[0]); BUBBLE5(m[1]); BUBBLE5(m[2]);                   \
            BUBBLE5(m[3]); BUBBLE5(m[4]);                                  \
        }                                                                  \
        __syncthreads();                                                   \
    }

__global__ void __launch_bounds__(K1_THREADS, 3)
scan_and_gemm(const float* __restrict__ pos,
              const float* __restrict__ x,
              const float* __restrict__ W)
{
    extern __shared__ float smem[];
    const int tid  = threadIdx.x;
    const int warp = tid >> 5;
    const int lane = tid & 31;
    const int bmod = (int)(blockIdx.x % 3);

    if (bmod < 2) {
        // ================= SCAN ROLE =================
        float4* pos_s  = (float4*)smem;                    // [2048] .w = -0.5|p|^2
        float*  m_s    = (float*)(pos_s + HALF_C);         // [8*32*5]
        float*  base_s = m_s + 8 * 32 * 5;                 // [32*5]
        float*  tau_s  = base_s + 32 * 5;                  // [32]

        const int sid  = (int)(blockIdx.x / 3) * 2 + bmod; // 0..511
        const int rg   = sid >> 1;
        const int half = sid & 1;
        const int r0   = rg * 32;
        const int b    = r0 >> 12;
        const int n0   = r0 & (N_PTS - 1);
        const int cb   = half * HALF_C;

        const float* pb = pos + ((size_t)b * N_PTS + cb) * 3;
        const float4* pb4 = (const float4*)pb;
        for (int g = tid; g < HALF_C / 4; g += K1_THREADS) {
            float4 a = pb4[3*g + 0];
            float4 c = pb4[3*g + 1];
            float4 d = pb4[3*g + 2];
            float4 q;
            q.x = a.x; q.y = a.y; q.z = a.z;
            q.w = -0.5f * fmaf(q.z, q.z, fmaf(q.y, q.y, q.x * q.x));
            pos_s[4*g + 0] = q;
            q.x = a.w; q.y = c.x; q.z = c.y;
            q.w = -0.5f * fmaf(q.z, q.z, fmaf(q.y, q.y, q.x * q.x));
            pos_s[4*g + 1] = q;
            q.x = c.z; q.y = c.w; q.z = d.x;
            q.w = -0.5f * fmaf(q.z, q.z, fmaf(q.y, q.y, q.x * q.x));
            pos_s[4*g + 2] = q;
            q.x = d.y; q.y = d.z; q.z = d.w;
            q.w = -0.5f * fmaf(q.z, q.z, fmaf(q.y, q.y, q.x * q.x));
            pos_s[4*g + 3] = q;
        }
        __syncthreads();

        const float* pr = pos + ((size_t)b * N_PTS + n0 + lane) * 3;
        float Px = __ldg(pr), Py = __ldg(pr + 1), Pz = __ldg(pr + 2);
        const float Pw2 = fmaf(Pz, Pz, fmaf(Py, Py, Px * Px));

        const float INF = __int_as_float(0x7f800000);
        float s0 = INF, s1 = INF, s2 = INF, s3 = INF, s4 = INF;

        const int base = warp * SB_SLICE;

        // phase 1: unconditional (32 cands/warp -> 512 samples/half)
        #pragma unroll 8
        for (int jj = 0; jj < SB_L1; jj++) {
            const int j = base + jj;
            float4 q = pos_s[j];
            float t   = fmaf(Px, q.x, fmaf(Py, q.y, fmaf(Pz, q.z, q.w)));
            float d2c = fmaf(-2.0f, t, Pw2);
            float k   = __int_as_float((__float_as_int(d2c) & 0xFFFFF000) | (cb + j));
            BUBBLE5(k);
        }

        TREEMERGE();

        if (warp == 0) {
            float* bs = base_s + lane * 5;
            bs[0] = s0; bs[1] = s1; bs[2] = s2; bs[3] = s3; bs[4] = s4;
            tau_s[lane] = __int_as_float((__float_as_int(s4) & 0xFFFFF000) + 0x1000);
        }
        __syncthreads();

        const float tau = tau_s[lane];

        // phase 2: filtered
        s0 = INF; s1 = INF; s2 = INF; s3 = INF; s4 = INF;
        #pragma unroll 8
        for (int jj = SB_L1; jj < SB_SLICE; jj++) {
            const int j = base + jj;
            float4 q = pos_s[j];
            float t   = fmaf(Px, q.x, fmaf(Py, q.y, fmaf(Pz, q.z, q.w)));
            float d2c = fmaf(-2.0f, t, Pw2);
            if (d2c < tau) {
                float k = __int_as_float((__float_as_int(d2c) & 0xFFFFF000) | (cb + j));
                BUBBLE5(k);
            }
        }

        TREEMERGE();

        if (warp == 0) {
            const float* bs = base_s + lane * 5;
            BUBBLE5(bs[0]); BUBBLE5(bs[1]); BUBBLE5(bs[2]);
            BUBBLE5(bs[3]); BUBBLE5(bs[4]);

            // exact difference-form rerank of the 5 survivors (pos in smem)
            float cand[5] = { s0, s1, s2, s3, s4 };
            unsigned long long k[5];
            #pragma unroll
            for (int i = 0; i < 5; i++) {
                int jg = __float_as_int(cand[i]) & 0xFFF;   // within-batch index
                float4 q = pos_s[jg - cb];
                float dx = Px - q.x, dy = Py - q.y, dz = Pz - q.z;
                float d2 = fmaf(dz, dz, fmaf(dy, dy, dx * dx));
                k[i] = ((unsigned long long)__float_as_uint(d2) << 32) | (unsigned)jg;
            }
            SWP(k[0],k[1]) SWP(k[3],k[4]) SWP(k[2],k[4]) SWP(k[2],k[3]) SWP(k[0],k[3])
            SWP(k[0],k[2]) SWP(k[1],k[4]) SWP(k[1],k[3]) SWP(k[1],k[2])

            unsigned long long* dst = Top5x + ((size_t)(r0 + lane) * 2 + half) * 8;
            dst[0] = k[0]; dst[1] = k[1]; dst[2] = k[2];
            dst[3] = k[3]; dst[4] = k[4];
        }
    } else {
        // ========== GEMM ROLE: Z[rg*64..+64][colh*64..+64], 4 rows/warp ==========
        float2* W2_s = (float2*)smem;                      // [128][32] float2 = 32 KB
        float*  x_s  = (float*)(W2_s + DIM * 32);          // [64][128] = 32 KB

        const int gid  = (int)(blockIdx.x / 3);            // 0..255
        const int rg   = gid >> 1;
        const int colh = gid & 1;
        const int g0   = rg * 64;

        // W half: lane p holds cols (colh*64 + 2p, 2p+1) for each d
        const float2* W2 = (const float2*)W;
        #pragma unroll
        for (int i = tid; i < DIM * 32; i += K1_THREADS) {
            int d = i >> 5, p = i & 31;
            W2_s[i] = __ldg(&W2[d * 64 + colh * 32 + p]);
        }
        const float4* xg = (const float4*)x + (size_t)g0 * 32;
        float4* xs4 = (float4*)x_s;
        #pragma unroll
        for (int i = tid; i < 64 * 32; i += K1_THREADS) xs4[i] = __ldg(&xg[i]);
        __syncthreads();

        const float* xr = x_s + warp * 4 * DIM;            // 4 rows per warp

        float2 a0 = make_float2(0.f, 0.f);
        float2 a1 = a0, a2 = a0, a3 = a0;

        #pragma unroll 4
        for (int d = 0; d < DIM; d++) {
            float2 wv = W2_s[d * 32 + lane];               // conflict-free LDS.64
            float y0 = xr[d];
            float y1 = xr[d + DIM];
            float y2 = xr[d + 2*DIM];
            float y3 = xr[d + 3*DIM];
            a0.x = fmaf(y0, wv.x, a0.x); a0.y = fmaf(y0, wv.y, a0.y);
            a1.x = fmaf(y1, wv.x, a1.x); a1.y = fmaf(y1, wv.y, a1.y);
            a2.x = fmaf(y2, wv.x, a2.x); a2.y = fmaf(y2, wv.y, a2.y);
            a3.x = fmaf(y3, wv.x, a3.x); a3.y = fmaf(y3, wv.y, a3.y);
        }

        float2* Z2 = (float2*)Z_buf;
        const size_t r = (size_t)g0 + warp * 4;
        const size_t c = (size_t)colh * 32 + lane;         // float2 col index
        Z2[(r + 0) * 64 + c] = a0;
        Z2[(r + 1) * 64 + c] = a1;
        Z2[(r + 2) * 64 + c] = a2;
        Z2[(r + 3) * 64 + c] = a3;
    }
}

// ---------------- kernel 2: merge sorted halves, weights, gather (R10, 6.2us) ----------------
#define GC_THREADS 256
#define GC_WARPS   8           // one row per warp

__global__ void __launch_bounds__(GC_THREADS, 8)
finish_gather(const float* __restrict__ bias,
              float* __restrict__ out)
{
    const int tid  = threadIdx.x;
    const int warp = tid >> 5;
    const int lane = tid & 31;
    const int row  = blockIdx.x * GC_WARPS + warp;     // global row (b*4096+n)
    const int b    = row >> 12;

    // two sorted 5-lists; top-4 of union lies in the first 4 of each
    const unsigned long long* t = Top5x + (size_t)row * 16;
    unsigned long long A0 = __ldg(&t[0]),  A1 = __ldg(&t[1]),
                       A2 = __ldg(&t[2]),  A3 = __ldg(&t[3]);
    unsigned long long B0 = __ldg(&t[8]),  B1 = __ldg(&t[9]),
                       B2 = __ldg(&t[10]), B3 = __ldg(&t[11]);

    float w0,w1,w2,w3; int i0,i1,i2,i3;
    #pragma unroll
    for (int r = 0; r < TOPK; r++) {
        bool ta = A0 < B0;
        unsigned long long v = ta ? A0 : B0;
        if (ta) { A0 = A1; A1 = A2; A2 = A3; A3 = ~0ull; }
        else    { B0 = B1; B1 = B2; B2 = B3; B3 = ~0ull; }
        float d2 = __uint_as_float((unsigned)(v >> 32));
        float ww = expf(-0.5f * (d2 + 1e-8f));
        int   jj = (int)(v & 0xFFFFFFFFull);
        if      (r == 0) { w0 = ww; i0 = jj; }
        else if (r == 1) { w1 = ww; i1 = jj; }
        else if (r == 2) { w2 = ww; i2 = jj; }
        else             { w3 = ww; i3 = jj; }
    }
    float inv = 1.0f / (((w0 + w1) + w2) + w3 + 1e-8f);
    w0 *= inv; w1 *= inv; w2 *= inv; w3 *= inv;

    // gather Z rows + bias
    const float4* Z4 = (const float4*)Z_buf + (size_t)b * N_PTS * 32;
    float4 acc = __ldg(&((const float4*)bias)[lane]);
    float4 z0 = Z4[(size_t)i0 * 32 + lane];
    float4 z1 = Z4[(size_t)i1 * 32 + lane];
    float4 z2 = Z4[(size_t)i2 * 32 + lane];
    float4 z3 = Z4[(size_t)i3 * 32 + lane];
    acc.x = fmaf(w0,z0.x, fmaf(w1,z1.x, fmaf(w2,z2.x, fmaf(w3,z3.x, acc.x))));
    acc.y = fmaf(w0,z0.y, fmaf(w1,z1.y, fmaf(w2,z2.y, fmaf(w3,z3.y, acc.y))));
    acc.z = fmaf(w0,z0.z, fmaf(w1,z1.z, fmaf(w2,z2.z, fmaf(w3,z3.z, acc.z))));
    acc.w = fmaf(w0,z0.w, fmaf(w1,z1.w, fmaf(w2,z2.w, fmaf(w3,z3.w, acc.w))));
    ((float4*)out)[(size_t)row * 32 + lane] = acc;
}

extern "C" void kernel_launch(void* const* d_in, const int* in_sizes, int n_in,
                              void* d_out, int out_size)
{
    const float* x    = (const float*)d_in[0];
    const float* pos  = (const float*)d_in[1];
    const float* W    = (const float*)d_in[2];
    const float* bias = (const float*)d_in[3];
    float* out        = (float*)d_out;

    const int rows = in_sizes[1] / 3;                  // B * N = 8192

    // K1: 512 scan + 256 GEMM blocks, interleaved (blockIdx % 3)
    const size_t smemScan = (size_t)HALF_C * 16 + 8*32*5*4 + 32*5*4 + 32*4;   // 38656
    const size_t smemGemm = (size_t)DIM * 32 * 8 + (size_t)64 * DIM * 4;      // 65536
    const size_t smem1 = smemScan > smemGemm ? smemScan : smemGemm;           // 65536
    cudaFuncSetAttribute(scan_and_gemm, cudaFuncAttributeMaxDynamicSharedMemorySize, (int)smem1);
    const int n_blocks = (rows / 32) * 2 + rows / 64 / 2 * 1;                 // 512 + 128? -> compute directly
    scan_and_gemm<<<768, K1_THREADS, smem1>>>(pos, x, W);

    // K2: merge + weights + gather
    finish_gather<<<rows / GC_WARPS, GC_THREADS>>>(bias, out);
}